// round 15
// baseline (speedup 1.0000x reference)
#include <cuda_runtime.h>
#include <math.h>

#define H 128
#define MAXN 100000
#define MAXE 200000
#define NBUCK 21   // levels 1..7 x 3 gate types
#define ECAP 4096  // dense edges per bucket
#define NCAP 8192  // nodes per bucket

#define NB_MAIN 147
#define NMLP 84    // 28 blocks per gate type
#define NGRU 63    // 21 blocks per gate type
#define MAIN_SMEM_BYTES (55552 * 4)   // GRU role: 49152+2304+4096 floats

// ---------------- static device scratch (allocation-free) ----------------
__device__ float g_msg[MAXN * H];
__device__ float g_comb[6 * H];
__device__ float g_T[3 * 6 * H];
__device__ float g_mt[3 * 6 * H];
__device__ float g_gv[3 * 6 * 384];
__device__ float g_wihT[3 * H * 384];
__device__ int   g_ebuck[NBUCK * ECAP];
__device__ int   g_nbuck[NBUCK * NCAP];
__device__ int   g_tc[MAXN * 6];
__device__ int   g_dcnt[MAXN];
__device__ int   g_ecur[NBUCK], g_ncur[NBUCK], g_ncur2[NBUCK];
__device__ unsigned g_bar_gen = 0;
__device__ unsigned g_bar_cnt = 0;

__device__ __forceinline__ int gimap(int g) {
    if (g == 3) return 0;
    if (g == 2) return 1;
    if (g == 5) return 2;
    return -1;
}

__device__ __forceinline__ float4 relu4(float4 a) {
    a.x = fmaxf(a.x, 0.f); a.y = fmaxf(a.y, 0.f);
    a.z = fmaxf(a.z, 0.f); a.w = fmaxf(a.w, 0.f);
    return a;
}

__device__ __forceinline__ float sigm(float x) { return 1.f / (1.f + __expf(-x)); }

__device__ __forceinline__ void fma4(float4& acc, float s, float4 v) {
    acc.x += s * v.x; acc.y += s * v.y; acc.z += s * v.z; acc.w += s * v.w;
}

// sense-reversing software grid barrier (147 blocks, 1/SM => single wave)
__device__ __forceinline__ void grid_sync() {
    __syncthreads();
    if (threadIdx.x == 0) {
        unsigned gen = atomicAdd(&g_bar_gen, 0u);
        __threadfence();
        if (atomicAdd(&g_bar_cnt, 1u) == NB_MAIN - 1) {
            g_bar_cnt = 0;
            __threadfence();
            atomicAdd(&g_bar_gen, 1u);
        } else {
            while (atomicAdd(&g_bar_gen, 0u) == gen) { __nanosleep(64); }
        }
        __threadfence();
    }
    __syncthreads();
}

// ---------------- prep kernels ----------------

// zero tc/dcnt + bucket counters
__global__ void k_zero() {
    int i = blockIdx.x * blockDim.x + threadIdx.x;
    if (i < MAXN * 6) g_tc[i] = 0;
    if (i < MAXN) g_dcnt[i] = 0;
    if (i < NBUCK) { g_ecur[i] = 0; g_ncur[i] = 0; g_ncur2[i] = NCAP; }
}

// comb + T + mt in one kernel (grid (6,3), 128 threads)
__global__ void k_prep(const float* __restrict__ Ws, const float* __restrict__ Wt,
                       const float* __restrict__ hsW, const float* __restrict__ hsb,
                       const float* __restrict__ w1, const float* __restrict__ b1,
                       const float* __restrict__ w2, const float* __restrict__ b2,
                       const float* __restrict__ w3, const float* __restrict__ b3) {
    __shared__ float bufA[H], bufB[H];
    int g = blockIdx.x, gi = blockIdx.y, h = threadIdx.x;
    float acc = hsb[h];
#pragma unroll 8
    for (int k = 0; k < H; k++) {
        acc += Ws[g * H + k] * hsW[k * H + h];
        acc += Wt[g * H + k] * hsW[(H + k) * H + h];
    }
    if (gi == 0) g_comb[g * H + h] = acc;
    bufA[h] = acc;
    __syncthreads();
    const float* W1 = w1 + gi * 256 * H;    // top half (hs part)
    float t = b1[gi * H + h];
#pragma unroll 8
    for (int k = 0; k < H; k++) t += bufA[k] * W1[k * H + h];
    g_T[(gi * 6 + g) * H + h] = t;
    bufB[h] = fmaxf(t, 0.f);
    __syncthreads();
    const float* W2 = w2 + gi * H * H;
    float a2 = b2[gi * H + h];
#pragma unroll 8
    for (int k = 0; k < H; k++) a2 += bufB[k] * W2[k * H + h];
    bufA[h] = fmaxf(a2, 0.f);
    __syncthreads();
    const float* W3 = w3 + gi * H * H;
    float a3 = b3[gi * H + h];
#pragma unroll 8
    for (int k = 0; k < H; k++) a3 += bufA[k] * W3[k * H + h];
    g_mt[(gi * 6 + g) * H + h] = a3;
}

// wihT[gi][k][j] = gru_wih[gi][j][k]
__global__ void k_transpose(const float* __restrict__ wih) {
    int idx = blockIdx.x * blockDim.x + threadIdx.x;
    if (idx >= 3 * 384 * H) return;
    int k  = idx % H;
    int j  = (idx / H) % 384;
    int gi = idx / (384 * H);
    g_wihT[(gi * H + k) * 384 + j] = wih[(gi * 384 + j) * H + k];
}

// gv[gi][g][j] = mt[gi][g] @ wih[gi]^T
__global__ void k_gv() {
    __shared__ float mrow[H];
    int g = blockIdx.x, gi = blockIdx.y, j = threadIdx.x;
    if (j < H) mrow[j] = g_mt[(gi * 6 + g) * H + j];
    __syncthreads();
    const float* WT = g_wihT + gi * H * 384;
    float acc = 0.f;
#pragma unroll 8
    for (int k = 0; k < H; k++) acc += mrow[k] * WT[k * 384 + j];
    g_gv[(gi * 6 + g) * 384 + j] = acc;
}

// single edge pass: dense -> bucket + dcnt; trivial -> tc counts
__global__ void k_edges(const int* __restrict__ ei, const int* __restrict__ gate,
                        const int* __restrict__ lvl, int e) {
    int i = blockIdx.x * blockDim.x + threadIdx.x;
    if (i >= e) return;
    int d = ei[e + i];
    int gi = gimap(gate[d]); int lv = lvl[d];
    if (gi < 0 || lv < 1) return;
    int s = ei[i];
    int sg = gate[s];
    int sgi = gimap(sg); int slv = lvl[s];
    int b = (lv - 1) * 3 + gi;
    if (sgi >= 0 && slv >= 1 && slv < lv) {
        int pos = atomicAdd(&g_ecur[b], 1);
        if (pos < ECAP) g_ebuck[b * ECAP + pos] = i;
        atomicAdd(&g_dcnt[d], 1);
    } else {
        atomicAdd(&g_tc[d * 6 + sg], 1);
    }
}

// node pass: dense-receiving front, trivial-only back
__global__ void k_nodes(const int* __restrict__ gate, const int* __restrict__ lvl,
                        int n) {
    int i = blockIdx.x * blockDim.x + threadIdx.x;
    if (i >= n) return;
    int gi = gimap(gate[i]); int lv = lvl[i];
    if (gi < 0 || lv < 1) return;
    int b = (lv - 1) * 3 + gi;
    if (g_dcnt[i] > 0) {
        int pos = atomicAdd(&g_ncur[b], 1);
        if (pos < NCAP) g_nbuck[b * NCAP + pos] = i;
    } else {
        int pos = atomicAdd(&g_ncur2[b], -1) - 1;
        if (pos >= 0) g_nbuck[b * NCAP + pos] = i;
    }
}

// hs gather; hf=0 for non-bucketed; msg=0 for dense-receiving
__global__ void k_init(const int* __restrict__ gate, const int* __restrict__ lvl,
                       float* __restrict__ hs, float* __restrict__ hf, int n) {
    int idx = blockIdx.x * blockDim.x + threadIdx.x;
    if (idx >= n * 32) return;
    int node = idx >> 5, c4 = idx & 31;
    int g = gate[node];
    float4 v = *(const float4*)&g_comb[g * H + c4 * 4];
    ((float4*)hs)[idx] = v;
    float4 z = make_float4(0.f, 0.f, 0.f, 0.f);
    bool buck = (gimap(g) >= 0) && (lvl[node] >= 1);
    if (!buck) ((float4*)hf)[idx] = z;
    else if (g_dcnt[node] > 0) ((float4*)g_msg)[idx] = z;
}

// ---------------- persistent main kernel ----------------
// 147 blocks, 1/SM. Blocks 0..83: MLP role (gi = bid%3, 28 each).
// Blocks 84..146: GRU role (gi = (bid-84)%3, 21 each).
// Schedule: [GRU: all trivial-only hf] sync  then for lv=2..7:
//   [MLP: dense edges -> msg] sync  [GRU: dense-recv nodes -> hf] sync

__global__ void __launch_bounds__(256, 1) k_main(
        const int* __restrict__ ei, const int* __restrict__ gate,
        const float* __restrict__ w1,
        const float* __restrict__ w2, const float* __restrict__ b2,
        const float* __restrict__ w3, const float* __restrict__ b3,
        const float* __restrict__ bih, const float* __restrict__ bhh,
        float* __restrict__ hf, int e) {
    extern __shared__ float sm[];
    int bid = blockIdx.x;
    int tid = threadIdx.x, lane = tid & 31, wl = tid >> 5;
    int c = lane * 4;

    if (bid < NMLP) {
        // ================= MLP role =================
        int gi = bid % 3, sub = bid / 3;
        float* sW1 = sm;           // 16384
        float* sW2 = sm + 16384;   // 16384
        float* sW3 = sm + 32768;   // 16384
        float* sT  = sm + 49152;   // 768
        float* sX  = sm + 49920;   // 8*4*128
        {
            const float4* s1 = (const float4*)(w1 + gi * 256 * H + 128 * H);
            const float4* s2 = (const float4*)(w2 + gi * H * H);
            const float4* s3 = (const float4*)(w3 + gi * H * H);
            float4* d1 = (float4*)sW1; float4* d2 = (float4*)sW2; float4* d3 = (float4*)sW3;
#pragma unroll
            for (int i = tid; i < 4096; i += 256) {
                d1[i] = s1[i]; d2[i] = s2[i]; d3[i] = s3[i];
            }
            const float4* st = (const float4*)(g_T + gi * 6 * H);
            float4* dt = (float4*)sT;
            if (tid < 192) dt[tid] = st[tid];
        }
        __syncthreads();
        float4 bias2 = *(const float4*)&b2[gi * H + c];
        float4 bias3 = *(const float4*)&b3[gi * H + c];
        float* xw = sX + wl * 512;
        int w0 = sub * 8 + wl;                  // 0..223

        grid_sync();   // trivial-only hf ready
        for (int lv = 2; lv <= 7; lv++) {
            int b = (lv - 1) * 3 + gi;
            int hi = min(g_ecur[b], ECAP);
            const int* ebuck = &g_ebuck[b * ECAP];
            for (int p = w0 * 4; p < hi; p += 224 * 4) {
                int eid[4]; bool m[4];
                float4 a0, a1, a2, a3;
#pragma unroll
                for (int q = 0; q < 4; q++) {
                    int idx = p + q; m[q] = idx < hi;
                    if (!m[q]) idx = hi - 1;
                    eid[q] = ebuck[idx];
                }
                {
                    int s0 = ei[eid[0]], s1 = ei[eid[1]], s2 = ei[eid[2]], s3 = ei[eid[3]];
                    *(float4*)&xw[0 * 128 + c] = *(const float4*)&hf[s0 * H + c];
                    *(float4*)&xw[1 * 128 + c] = *(const float4*)&hf[s1 * H + c];
                    *(float4*)&xw[2 * 128 + c] = *(const float4*)&hf[s2 * H + c];
                    *(float4*)&xw[3 * 128 + c] = *(const float4*)&hf[s3 * H + c];
                    a0 = *(const float4*)&sT[gate[s0] * H + c];
                    a1 = *(const float4*)&sT[gate[s1] * H + c];
                    a2 = *(const float4*)&sT[gate[s2] * H + c];
                    a3 = *(const float4*)&sT[gate[s3] * H + c];
                }
                __syncwarp();
#pragma unroll 4
                for (int k = 0; k < 128; k++) {
                    float4 w = *(const float4*)&sW1[k * H + c];
                    fma4(a0, xw[0 * 128 + k], w); fma4(a1, xw[1 * 128 + k], w);
                    fma4(a2, xw[2 * 128 + k], w); fma4(a3, xw[3 * 128 + k], w);
                }
                a0 = relu4(a0); a1 = relu4(a1); a2 = relu4(a2); a3 = relu4(a3);
                __syncwarp();
                *(float4*)&xw[0 * 128 + c] = a0; *(float4*)&xw[1 * 128 + c] = a1;
                *(float4*)&xw[2 * 128 + c] = a2; *(float4*)&xw[3 * 128 + c] = a3;
                __syncwarp();
                a0 = bias2; a1 = bias2; a2 = bias2; a3 = bias2;
#pragma unroll 4
                for (int k = 0; k < 128; k++) {
                    float4 w = *(const float4*)&sW2[k * H + c];
                    fma4(a0, xw[0 * 128 + k], w); fma4(a1, xw[1 * 128 + k], w);
                    fma4(a2, xw[2 * 128 + k], w); fma4(a3, xw[3 * 128 + k], w);
                }
                a0 = relu4(a0); a1 = relu4(a1); a2 = relu4(a2); a3 = relu4(a3);
                __syncwarp();
                *(float4*)&xw[0 * 128 + c] = a0; *(float4*)&xw[1 * 128 + c] = a1;
                *(float4*)&xw[2 * 128 + c] = a2; *(float4*)&xw[3 * 128 + c] = a3;
                __syncwarp();
                a0 = bias3; a1 = bias3; a2 = bias3; a3 = bias3;
#pragma unroll 4
                for (int k = 0; k < 128; k++) {
                    float4 w = *(const float4*)&sW3[k * H + c];
                    fma4(a0, xw[0 * 128 + k], w); fma4(a1, xw[1 * 128 + k], w);
                    fma4(a2, xw[2 * 128 + k], w); fma4(a3, xw[3 * 128 + k], w);
                }
#pragma unroll
                for (int q = 0; q < 4; q++) {
                    if (!m[q]) break;
                    float4 a = (q == 0) ? a0 : (q == 1) ? a1 : (q == 2) ? a2 : a3;
                    int d = ei[e + eid[q]];
                    atomicAdd(&g_msg[d * H + c + 0], a.x);
                    atomicAdd(&g_msg[d * H + c + 1], a.y);
                    atomicAdd(&g_msg[d * H + c + 2], a.z);
                    atomicAdd(&g_msg[d * H + c + 3], a.w);
                }
                __syncwarp();
            }
            grid_sync();   // msg ready for GRU
            grid_sync();   // GRU wrote hf
        }
    } else {
        // ================= GRU role =================
        int gb = bid - NMLP, gi = gb % 3, sub = gb / 3;
        float* sWT = sm;                 // 49152
        float* sGV = sm + 49152;         // 2304
        float* sM  = sm + 51456;         // 8*4*128
        {
            const float4* src = (const float4*)(g_wihT + gi * H * 384);
            float4* dst = (float4*)sWT;
            for (int i = tid; i < 12288; i += 256) dst[i] = src[i];
            const float4* sv = (const float4*)(g_gv + gi * 6 * 384);
            float4* dv = (float4*)sGV;
            for (int i = tid; i < 576; i += 256) dv[i] = sv[i];
        }
        __syncthreads();
        const float* BI = bih + gi * 384;
        const float* BH = bhh + gi * 384;
        float4 cR, cZ, bN, hN;
        {
            float4 bR = *(const float4*)&BI[c];
            float4 bZ = *(const float4*)&BI[128 + c];
            bN = *(const float4*)&BI[256 + c];
            float4 hR = *(const float4*)&BH[c];
            float4 hZ = *(const float4*)&BH[128 + c];
            hN = *(const float4*)&BH[256 + c];
            cR = make_float4(bR.x + hR.x, bR.y + hR.y, bR.z + hR.z, bR.w + hR.w);
            cZ = make_float4(bZ.x + hZ.x, bZ.y + hZ.y, bZ.z + hZ.z, bZ.w + hZ.w);
        }
        float* mw = sM + wl * 512;
        int w0 = sub * 8 + wl;                  // 0..167

        // ---- upfront: ALL trivial-only nodes (static, all levels) ----
        for (int lv = 1; lv <= 7; lv++) {
            int b = (lv - 1) * 3 + gi;
            int t0 = max(g_ncur2[b], 0);
            const int* nbuck = &g_nbuck[b * NCAP];
            for (int p = t0 + w0 * 4; p < NCAP; p += 168 * 4) {
#pragma unroll
                for (int q = 0; q < 4; q++) {
                    int idx = p + q;
                    if (idx >= NCAP) break;
                    int v = nbuck[idx];
                    float4 aR = cR, aZ = cZ, aN = bN;
#pragma unroll
                    for (int g = 0; g < 6; g++) {
                        float f = (float)g_tc[v * 6 + g];
                        fma4(aR, f, *(const float4*)&sGV[g * 384 + c]);
                        fma4(aZ, f, *(const float4*)&sGV[g * 384 + 128 + c]);
                        fma4(aN, f, *(const float4*)&sGV[g * 384 + 256 + c]);
                    }
                    float4 o;
                    float r, z;
                    r = sigm(aR.x); z = sigm(aZ.x); o.x = (1.f - z) * tanhf(aN.x + r * hN.x);
                    r = sigm(aR.y); z = sigm(aZ.y); o.y = (1.f - z) * tanhf(aN.y + r * hN.y);
                    r = sigm(aR.z); z = sigm(aZ.z); o.z = (1.f - z) * tanhf(aN.z + r * hN.z);
                    r = sigm(aR.w); z = sigm(aZ.w); o.w = (1.f - z) * tanhf(aN.w + r * hN.w);
                    *(float4*)&hf[v * H + c] = o;
                }
            }
        }
        grid_sync();   // trivial-only hf ready

        for (int lv = 2; lv <= 7; lv++) {
            grid_sync();   // MLP msg ready
            int b = (lv - 1) * 3 + gi;
            int dc = min(g_ncur[b], NCAP);
            const int* nbuck = &g_nbuck[b * NCAP];
            for (int p = w0 * 4; p < dc; p += 168 * 4) {
                int v[4]; bool m[4];
#pragma unroll
                for (int q = 0; q < 4; q++) {
                    int idx = p + q; m[q] = idx < dc;
                    if (!m[q]) idx = dc - 1;
                    v[q] = nbuck[idx];
                }
                *(float4*)&mw[0 * 128 + c] = *(const float4*)&g_msg[v[0] * H + c];
                *(float4*)&mw[1 * 128 + c] = *(const float4*)&g_msg[v[1] * H + c];
                *(float4*)&mw[2 * 128 + c] = *(const float4*)&g_msg[v[2] * H + c];
                *(float4*)&mw[3 * 128 + c] = *(const float4*)&g_msg[v[3] * H + c];
                __syncwarp();
                float4 aR0 = cR, aR1 = cR, aR2 = cR, aR3 = cR;
                float4 aZ0 = cZ, aZ1 = cZ, aZ2 = cZ, aZ3 = cZ;
                float4 aN0 = bN, aN1 = bN, aN2 = bN, aN3 = bN;
#pragma unroll
                for (int g = 0; g < 6; g++) {
                    float4 vr = *(const float4*)&sGV[g * 384 + c];
                    float4 vz = *(const float4*)&sGV[g * 384 + 128 + c];
                    float4 vn = *(const float4*)&sGV[g * 384 + 256 + c];
                    float f0 = (float)g_tc[v[0] * 6 + g];
                    float f1 = (float)g_tc[v[1] * 6 + g];
                    float f2 = (float)g_tc[v[2] * 6 + g];
                    float f3 = (float)g_tc[v[3] * 6 + g];
                    fma4(aR0, f0, vr); fma4(aZ0, f0, vz); fma4(aN0, f0, vn);
                    fma4(aR1, f1, vr); fma4(aZ1, f1, vz); fma4(aN1, f1, vn);
                    fma4(aR2, f2, vr); fma4(aZ2, f2, vz); fma4(aN2, f2, vn);
                    fma4(aR3, f3, vr); fma4(aZ3, f3, vz); fma4(aN3, f3, vn);
                }
#pragma unroll 2
                for (int k = 0; k < 128; k++) {
                    float m0 = mw[0 * 128 + k], m1v = mw[1 * 128 + k];
                    float m2 = mw[2 * 128 + k], m3 = mw[3 * 128 + k];
                    float4 wr = *(const float4*)&sWT[k * 384 + c];
                    float4 wz = *(const float4*)&sWT[k * 384 + 128 + c];
                    float4 wn = *(const float4*)&sWT[k * 384 + 256 + c];
                    fma4(aR0, m0, wr); fma4(aZ0, m0, wz); fma4(aN0, m0, wn);
                    fma4(aR1, m1v, wr); fma4(aZ1, m1v, wz); fma4(aN1, m1v, wn);
                    fma4(aR2, m2, wr); fma4(aZ2, m2, wz); fma4(aN2, m2, wn);
                    fma4(aR3, m3, wr); fma4(aZ3, m3, wz); fma4(aN3, m3, wn);
                }
#pragma unroll
                for (int q = 0; q < 4; q++) {
                    if (!m[q]) break;
                    float4 aR = (q == 0) ? aR0 : (q == 1) ? aR1 : (q == 2) ? aR2 : aR3;
                    float4 aZ = (q == 0) ? aZ0 : (q == 1) ? aZ1 : (q == 2) ? aZ2 : aZ3;
                    float4 aN = (q == 0) ? aN0 : (q == 1) ? aN1 : (q == 2) ? aN2 : aN3;
                    float4 o;
                    float r, z;
                    r = sigm(aR.x); z = sigm(aZ.x); o.x = (1.f - z) * tanhf(aN.x + r * hN.x);
                    r = sigm(aR.y); z = sigm(aZ.y); o.y = (1.f - z) * tanhf(aN.y + r * hN.y);
                    r = sigm(aR.z); z = sigm(aZ.z); o.z = (1.f - z) * tanhf(aN.z + r * hN.z);
                    r = sigm(aR.w); z = sigm(aZ.w); o.w = (1.f - z) * tanhf(aN.w + r * hN.w);
                    *(float4*)&hf[v[q] * H + c] = o;
                }
                __syncwarp();
            }
            grid_sync();   // hf ready for next level's MLP
        }
    }
}

// ---------------- launch ----------------
extern "C" void kernel_launch(void* const* d_in, const int* in_sizes, int n_in,
                              void* d_out, int out_size) {
    const int*   gate = (const int*)d_in[0];
    const int*   lvl  = (const int*)d_in[1];
    const int*   ei   = (const int*)d_in[2];
    const float* Ws   = (const float*)d_in[3];
    const float* Wt   = (const float*)d_in[4];
    const float* hsW  = (const float*)d_in[5];
    const float* hsb  = (const float*)d_in[6];
    const float* w1   = (const float*)d_in[7];
    const float* b1   = (const float*)d_in[8];
    const float* w2   = (const float*)d_in[9];
    const float* b2   = (const float*)d_in[10];
    const float* w3   = (const float*)d_in[11];
    const float* b3   = (const float*)d_in[12];
    const float* wih  = (const float*)d_in[13];
    // d_in[14] = gru_whh: provably unused (h_old == 0 for every updated node)
    const float* bih  = (const float*)d_in[15];
    const float* bhh  = (const float*)d_in[16];

    int n = in_sizes[0];
    int e = in_sizes[2] / 2;

    float* hs = (float*)d_out;            // output: [hs (N*H) | hf (N*H)]
    float* hf = hs + (size_t)n * H;

    cudaFuncSetAttribute(k_main, cudaFuncAttributeMaxDynamicSharedMemorySize,
                         MAIN_SMEM_BYTES);

    k_zero<<<(MAXN * 6 + 255) / 256, 256>>>();
    k_prep<<<dim3(6, 3), H>>>(Ws, Wt, hsW, hsb, w1, b1, w2, b2, w3, b3);
    k_transpose<<<(3 * 384 * H + 255) / 256, 256>>>(wih);
    k_gv<<<dim3(6, 3), 384>>>();
    k_edges<<<(e + 255) / 256, 256>>>(ei, gate, lvl, e);
    k_nodes<<<(n + 255) / 256, 256>>>(gate, lvl, n);
    k_init<<<(n * 32 + 255) / 256, 256>>>(gate, lvl, hs, hf, n);
    k_main<<<NB_MAIN, 256, MAIN_SMEM_BYTES>>>(ei, gate, w1, w2, b2, w3, b3,
                                              bih, bhh, hf, e);
}